// round 2
// baseline (speedup 1.0000x reference)
#include <cuda_runtime.h>
#include <math.h>
#include <stdint.h>

#define N_P 33600
#define N_G 256
#define N_C 80
#define KK  13
#define LEN 16

// ---------------- scratch (device globals; no runtime allocation) ----------
__device__ float  g_lT [(size_t)N_C * N_P];   // logits, class-major
__device__ float  g_sT [(size_t)N_C * N_P];   // sigmoid(logit), class-major
__device__ float  g_mT [(size_t)N_C * N_P];   // max(l,0)+log1p(exp(-|l|)), class-major
__device__ float4 g_pk0[N_P];                 // pred bbox x1,y1,x2,y2
__device__ float4 g_pk1[N_P];                 // px, py, stride, +-area (sign = valid)
__device__ float4 g_gtbox [N_G];              // x1,y1,x2,y2
__device__ float4 g_gtmeta[N_G];              // area, cx, cy, pad
__device__ float4 g_vbox  [N_G];              // box for validity test (degenerate if pad==0)
__device__ int    g_glab  [N_G];
__device__ int    g_goff  [N_G];              // glab[j] * N_P
__device__ int    g_cnt [N_P];
__device__ int    g_mgt [N_P];

// ---------------- shared math helpers (identical in both consumers) --------
__device__ __forceinline__ float iou_of(float4 A, float Pw, float4 b, float area_b) {
    float area_a = fabsf(Pw);
    float ltx = fmaxf(A.x, b.x), lty = fmaxf(A.y, b.y);
    float rbx = fminf(A.z, b.z), rby = fminf(A.w, b.w);
    float w = fmaxf(rbx - ltx, 0.0f), h = fmaxf(rby - lty, 0.0f);
    float inter = w * h;
    float uni = (area_a + area_b) - inter;
    return __fdiv_rn(inter, fmaxf(uni, 1e-6f));
}

__device__ __forceinline__ float cost_of(float iou, float px, float py, float st,
                                         float cx, float cy,
                                         float l, float s, float mm) {
    float dx = px - cx, dy = py - cy;
    float d2 = __fmaf_rn(dx, dx, dy * dy);
    float dist = __fdiv_rn(__fsqrt_rn(d2), st);
    float scp = expf((dist - 3.0f) * 2.302585092994046f);   // 10^(dist-3)
    float d = iou - s;
    float scale = d * d;
    float bce = __fmaf_rn(-l, iou, mm);
    float ic = -logf(iou + 1e-7f) * 3.0f;
    return __fmaf_rn(bce, scale, ic) + scp;
}

// ---------------- kernel G: GT preprocessing -------------------------------
__global__ void prep_gt_kernel(const float* __restrict__ gtb,
                               const int*   __restrict__ glab) {
    int j = threadIdx.x;
    if (j < N_G) {
        float x1 = gtb[j*4+0], y1 = gtb[j*4+1];
        float x2 = gtb[j*4+2], y2 = gtb[j*4+3];
        g_gtbox[j] = make_float4(x1, y1, x2, y2);
        float area = (x2 - x1) * (y2 - y1);
        bool pad = ((x1 + y1) + (x2 + y2)) > 0.0f;
        g_gtmeta[j] = make_float4(area, (x1 + x2) * 0.5f, (y1 + y2) * 0.5f,
                                  pad ? 1.0f : 0.0f);
        g_vbox[j] = pad ? make_float4(x1, y1, x2, y2)
                        : make_float4(1e30f, 1e30f, -1e30f, -1e30f);
        int lab = glab[j];
        g_glab[j] = lab;
        g_goff[j] = lab * N_P;
    }
}

// ---------------- kernel S: sigmoid/softplus, transposed (tiled) -----------
__global__ void __launch_bounds__(256) prep_scores_kernel(const float* __restrict__ ps) {
    __shared__ float sh[80][33];
    int tid = threadIdx.x;
    int i0 = blockIdx.x * 32;
    // coalesced load of 32 rows x 80 classes
    const float* base = ps + (size_t)i0 * N_C;
    #pragma unroll
    for (int t = tid; t < 32 * 80; t += 256) {
        int i_loc = t / 80;
        int c = t - i_loc * 80;
        sh[c][i_loc] = base[t];
    }
    __syncthreads();
    int i_loc = tid & 31;
    int cbase = tid >> 5;
    #pragma unroll
    for (int cc = cbase; cc < 80; cc += 8) {
        float l = sh[cc][i_loc];
        float e = expf(-fabsf(l));
        float inv = __fdiv_rn(1.0f, 1.0f + e);
        float sig = (l >= 0.0f) ? inv : e * inv;
        float m = fmaxf(l, 0.0f) + log1pf(e);
        int o = cc * N_P + i0 + i_loc;
        g_lT[o] = l;
        g_sT[o] = sig;
        g_mT[o] = m;
    }
}

// ---------------- kernel P: pack prior data + valid mask + zero counters ---
__global__ void __launch_bounds__(256) prep_priors_kernel(const float* __restrict__ priors,
                                                          const float* __restrict__ pb) {
    __shared__ float4 svb[N_G];
    int tid = threadIdx.x;
    svb[tid] = g_vbox[tid];
    __syncthreads();
    int i = blockIdx.x * 256 + tid;
    if (i >= N_P) return;
    float4 PR = ((const float4*)priors)[i];
    float4 A  = ((const float4*)pb)[i];
    float px = PR.x, py = PR.y, st = PR.z;
    bool any = false;
    #pragma unroll 8
    for (int j = 0; j < N_G; j++) {
        float4 B = svb[j];
        any |= (px > B.x) && (py > B.y) && (px < B.z) && (py < B.w);
    }
    float area = (A.z - A.x) * (A.w - A.y);   // > 0 always (wh >= 8)
    g_pk0[i] = A;
    g_pk1[i] = make_float4(px, py, st, any ? area : -area);
    g_cnt[i] = 0;
}

// ---------------- bitonic top-16 merge primitives --------------------------
// iou list: descending values only
__device__ __forceinline__ void merge_iou(float* a, const float* o) {
    float c[LEN];
    #pragma unroll
    for (int k = 0; k < LEN; k++) c[k] = fmaxf(a[k], o[LEN-1-k]);
    #pragma unroll
    for (int s = LEN/2; s > 0; s >>= 1) {
        #pragma unroll
        for (int k = 0; k < LEN; k++) {
            if ((k & s) == 0) {
                float lo = c[k], hi = c[k+s];
                c[k]   = fmaxf(lo, hi);
                c[k+s] = fminf(lo, hi);
            }
        }
    }
    #pragma unroll
    for (int k = 0; k < LEN; k++) a[k] = c[k];
}

// cost list: ascending (value, index) lexicographic
__device__ __forceinline__ void merge_cost(float* v, int* ix,
                                           const float* ov, const int* oi) {
    float cv[LEN]; int ci[LEN];
    #pragma unroll
    for (int k = 0; k < LEN; k++) {
        float bv = ov[LEN-1-k]; int bi = oi[LEN-1-k];
        bool ta = (v[k] < bv) || (v[k] == bv && ix[k] < bi);
        cv[k] = ta ? v[k]  : bv;
        ci[k] = ta ? ix[k] : bi;
    }
    #pragma unroll
    for (int s = LEN/2; s > 0; s >>= 1) {
        #pragma unroll
        for (int k = 0; k < LEN; k++) {
            if ((k & s) == 0) {
                float av = cv[k], bv = cv[k+s];
                int   ai = ci[k], bi = ci[k+s];
                bool sw = (bv < av) || (bv == av && bi < ai);
                if (sw) { cv[k] = bv; ci[k] = bi; cv[k+s] = av; ci[k+s] = ai; }
            }
        }
    }
    #pragma unroll
    for (int k = 0; k < LEN; k++) { v[k] = cv[k]; ix[k] = ci[k]; }
}

__device__ __forceinline__ void shfl_merge(float* cv, int* ci, float* vi, int off) {
    float ov[LEN], ovi[LEN]; int oi[LEN];
    #pragma unroll
    for (int k = 0; k < LEN; k++) {
        ov [k] = __shfl_xor_sync(0xFFFFFFFFu, cv[k], off);
        oi [k] = __shfl_xor_sync(0xFFFFFFFFu, ci[k], off);
        ovi[k] = __shfl_xor_sync(0xFFFFFFFFu, vi[k], off);
    }
    merge_cost(cv, ci, ov, oi);
    merge_iou(vi, ovi);
}

// ---------------- kernel F: fused pairwise iou/cost + per-GT top-13 --------
__global__ void __launch_bounds__(256) fused_topk_kernel() {
    int j = blockIdx.x, tid = threadIdx.x;
    float4 b  = g_gtbox[j];
    float4 m4 = g_gtmeta[j];
    int goff = g_goff[j];
    const float* __restrict__ lrow = g_lT + goff;
    const float* __restrict__ srow = g_sT + goff;
    const float* __restrict__ mrow = g_mT + goff;

    float vi[LEN]; float cv[LEN]; int ci[LEN];
    #pragma unroll
    for (int k = 0; k < LEN; k++) { vi[k] = -1.0f; cv[k] = 3.4e38f; ci[k] = 0x7FFFFFFF; }

    #pragma unroll 2
    for (int i = tid; i < N_P; i += 256) {
        float4 A = g_pk0[i];
        float4 P = g_pk1[i];
        float iou = iou_of(A, P.w, b, m4.x);
        if (iou > vi[LEN-1]) {
            vi[LEN-1] = iou;
            #pragma unroll
            for (int k = LEN-1; k > 0; k--)
                if (vi[k] > vi[k-1]) { float t = vi[k-1]; vi[k-1] = vi[k]; vi[k] = t; }
        }
        float cost;
        if (P.w > 0.0f) {
            float l = lrow[i], s = srow[i], mm = mrow[i];
            cost = cost_of(iou, P.x, P.y, P.z, m4.y, m4.z, l, s, mm);
        } else {
            cost = 1e8f;
        }
        if (cost < cv[LEN-1]) {          // equal keeps earlier (lower) index: stable
            cv[LEN-1] = cost; ci[LEN-1] = i;
            #pragma unroll
            for (int k = LEN-1; k > 0; k--)
                if (cv[k] < cv[k-1]) {
                    float t = cv[k-1]; cv[k-1] = cv[k]; cv[k] = t;
                    int   q = ci[k-1]; ci[k-1] = ci[k]; ci[k] = q;
                }
        }
    }

    // warp butterfly merge (5 levels)
    #pragma unroll
    for (int off = 1; off < 32; off <<= 1) shfl_merge(cv, ci, vi, off);

    // cross-warp merge via shared (8 warp lists)
    __shared__ float s_cv[8][LEN]; __shared__ int s_ci[8][LEN]; __shared__ float s_vi[8][LEN];
    int w = tid >> 5, lane = tid & 31;
    if (lane == 0) {
        #pragma unroll
        for (int k = 0; k < LEN; k++) { s_cv[w][k] = cv[k]; s_ci[w][k] = ci[k]; s_vi[w][k] = vi[k]; }
    }
    __syncthreads();
    if (w == 0) {
        if (lane < 8) {
            #pragma unroll
            for (int k = 0; k < LEN; k++) { cv[k] = s_cv[lane][k]; ci[k] = s_ci[lane][k]; vi[k] = s_vi[lane][k]; }
        } else {
            #pragma unroll
            for (int k = 0; k < LEN; k++) { cv[k] = 3.4e38f; ci[k] = 0x7FFFFFFF; vi[k] = -1.0f; }
        }
        shfl_merge(cv, ci, vi, 1);
        shfl_merge(cv, ci, vi, 2);
        shfl_merge(cv, ci, vi, 4);
        if (lane == 0) {
            float sum = 0.0f;
            #pragma unroll
            for (int k = 0; k < KK; k++) sum += vi[k];
            int ks = (int)sum;
            if (ks < 1)  ks = 1;
            if (ks > KK) ks = KK;
            #pragma unroll
            for (int k = 0; k < KK; k++) {
                if (k < ks) {
                    int i = ci[k];
                    atomicAdd(&g_cnt[i], 1);
                    g_mgt[i] = j;        // racy only when cnt>1 (recomputed in resolve)
                }
            }
        }
    }
}

// ---------------- kernel R: resolve per-prior assignment -------------------
__global__ void __launch_bounds__(256) resolve_kernel(float* __restrict__ out) {
    int i = blockIdx.x * 256 + threadIdx.x;
    if (i >= N_P) return;
    float4 P = g_pk1[i];
    float4 A = g_pk0[i];
    bool valid = P.w > 0.0f;
    int c = g_cnt[i];
    int gsel = 0;
    bool fg = false;
    if (c == 1) {
        gsel = g_mgt[i];
        fg = true;
    } else if (c > 1) {
        fg = true;
        if (valid) {
            float best = 3.4e38f;
            for (int j = 0; j < N_G; j++) {
                float4 bb = g_gtbox[j]; float4 mm4 = g_gtmeta[j];
                float io = iou_of(A, P.w, bb, mm4.x);
                int off = g_goff[j];
                float l = g_lT[off + i], s = g_sT[off + i], mm = g_mT[off + i];
                float cost = cost_of(io, P.x, P.y, P.z, mm4.y, mm4.z, l, s, mm);
                if (cost < best) { best = cost; gsel = j; }   // first-min, lowest index
            }
        }
    }
    float iou = 0.0f;
    if (fg) {
        float4 bb = g_gtbox[gsel]; float4 mm4 = g_gtmeta[gsel];
        iou = iou_of(A, P.w, bb, mm4.x);
    }
    bool fin = fg && valid;
    out[i]           = fin ? (float)(gsel + 1)   : 0.0f;
    out[N_P + i]     = fin ? iou                 : -1e8f;
    out[2*N_P + i]   = fin ? (float)g_glab[gsel] : -1.0f;
}

// ---------------- launch ----------------------------------------------------
extern "C" void kernel_launch(void* const* d_in, const int* in_sizes, int n_in,
                              void* d_out, int out_size) {
    const float* pred_scores = (const float*)d_in[0];
    const float* priors      = (const float*)d_in[1];
    const float* pred_bboxes = (const float*)d_in[2];
    const float* gt_bboxes   = (const float*)d_in[3];
    const int*   gt_labels   = (const int*)  d_in[4];

    prep_gt_kernel<<<1, 256>>>(gt_bboxes, gt_labels);
    prep_scores_kernel<<<N_P / 32, 256>>>(pred_scores);
    prep_priors_kernel<<<(N_P + 255) / 256, 256>>>(priors, pred_bboxes);
    fused_topk_kernel<<<N_G, 256>>>();
    resolve_kernel<<<(N_P + 255) / 256, 256>>>((float*)d_out);
}

// round 3
// speedup vs baseline: 1.4839x; 1.4839x over previous
#include <cuda_runtime.h>
#include <math.h>
#include <stdint.h>

#define N_P 33600
#define N_G 256
#define N_C 80
#define KK  13
#define LEN 16
#define SPLIT 2
#define CHUNK (N_P / SPLIT)

typedef unsigned long long u64;

// ---------------- scratch (device globals; no runtime allocation) ----------
__device__ float2 g_pc [(size_t)N_G * N_P];   // column-major {iou, cost}
__device__ float  g_lT [(size_t)N_C * N_P];   // logits, class-major
__device__ float  g_sT [(size_t)N_C * N_P];   // sigmoid(logit), class-major
__device__ float  g_mT [(size_t)N_C * N_P];   // max(l,0)+log1p(exp(-|l|))
__device__ float4 g_pk0[N_P];                 // pred bbox x1,y1,x2,y2
__device__ float4 g_pk1[N_P];                 // px, py, stride, +-area (sign = valid)
__device__ float4 g_gtbox [N_G];
__device__ float4 g_gtmeta[N_G];              // area, cx, cy, pad
__device__ float4 g_vbox  [N_G];
__device__ int    g_glab  [N_G];
__device__ int    g_goff  [N_G];              // glab[j] * N_P
__device__ int    g_cnt [N_P];
__device__ int    g_mgt [N_P];
__device__ u64    g_skey[N_G * SPLIT * 16];   // per-part sorted cost keys
__device__ float  g_siou[N_G * SPLIT * 16];   // per-part sorted ious (desc)

// ---------------- shared math helpers ---------------------------------------
__device__ __forceinline__ float iou_of(float4 A, float Pw, float4 b, float area_b) {
    float area_a = fabsf(Pw);
    float ltx = fmaxf(A.x, b.x), lty = fmaxf(A.y, b.y);
    float rbx = fminf(A.z, b.z), rby = fminf(A.w, b.w);
    float w = fmaxf(rbx - ltx, 0.0f), h = fmaxf(rby - lty, 0.0f);
    float inter = w * h;
    float uni = (area_a + area_b) - inter;
    return __fdiv_rn(inter, fmaxf(uni, 1e-6f));
}

__device__ __forceinline__ float cost_of(float iou, float px, float py, float st,
                                         float cx, float cy,
                                         float l, float s, float mm) {
    float dx = px - cx, dy = py - cy;
    float d2 = __fmaf_rn(dx, dx, dy * dy);
    float dist = __fdiv_rn(__fsqrt_rn(d2), st);
    float scp = expf((dist - 3.0f) * 2.302585092994046f);   // 10^(dist-3)
    float d = iou - s;
    float scale = d * d;
    float bce = __fmaf_rn(-l, iou, mm);
    float ic = -logf(iou + 1e-7f) * 3.0f;
    return __fmaf_rn(bce, scale, ic) + scp;
}

// ---------------- kernel G: GT preprocessing -------------------------------
__global__ void prep_gt_kernel(const float* __restrict__ gtb,
                               const int*   __restrict__ glab) {
    int j = threadIdx.x;
    if (j < N_G) {
        float x1 = gtb[j*4+0], y1 = gtb[j*4+1];
        float x2 = gtb[j*4+2], y2 = gtb[j*4+3];
        g_gtbox[j] = make_float4(x1, y1, x2, y2);
        float area = (x2 - x1) * (y2 - y1);
        bool pad = ((x1 + y1) + (x2 + y2)) > 0.0f;
        g_gtmeta[j] = make_float4(area, (x1 + x2) * 0.5f, (y1 + y2) * 0.5f,
                                  pad ? 1.0f : 0.0f);
        g_vbox[j] = pad ? make_float4(x1, y1, x2, y2)
                        : make_float4(1e30f, 1e30f, -1e30f, -1e30f);
        int lab = glab[j];
        g_glab[j] = lab;
        g_goff[j] = lab * N_P;
    }
}

// ---------------- kernel S: sigmoid/softplus, transposed (tiled) -----------
__global__ void __launch_bounds__(256) prep_scores_kernel(const float* __restrict__ ps) {
    __shared__ float sh[80][33];
    int tid = threadIdx.x;
    int i0 = blockIdx.x * 32;
    const float* base = ps + (size_t)i0 * N_C;
    #pragma unroll
    for (int t = tid; t < 32 * 80; t += 256) {
        int i_loc = t / 80;
        int c = t - i_loc * 80;
        sh[c][i_loc] = base[t];
    }
    __syncthreads();
    int i_loc = tid & 31;
    int cbase = tid >> 5;
    #pragma unroll
    for (int cc = cbase; cc < 80; cc += 8) {
        float l = sh[cc][i_loc];
        float e = expf(-fabsf(l));
        float inv = __fdiv_rn(1.0f, 1.0f + e);
        float sig = (l >= 0.0f) ? inv : e * inv;
        float m = fmaxf(l, 0.0f) + log1pf(e);
        int o = cc * N_P + i0 + i_loc;
        g_lT[o] = l;
        g_sT[o] = sig;
        g_mT[o] = m;
    }
}

// ---------------- kernel P: pack priors + valid mask + zero counters -------
__global__ void __launch_bounds__(256) prep_priors_kernel(const float* __restrict__ priors,
                                                          const float* __restrict__ pb) {
    __shared__ float4 svb[N_G];
    int tid = threadIdx.x;
    svb[tid] = g_vbox[tid];
    __syncthreads();
    int i = blockIdx.x * 256 + tid;
    if (i >= N_P) return;
    float4 PR = ((const float4*)priors)[i];
    float4 A  = ((const float4*)pb)[i];
    float px = PR.x, py = PR.y, st = PR.z;
    bool any = false;
    #pragma unroll 8
    for (int j = 0; j < N_G; j++) {
        float4 B = svb[j];
        any |= (px > B.x) && (py > B.y) && (px < B.z) && (py < B.w);
    }
    float area = (A.z - A.x) * (A.w - A.y);
    g_pk0[i] = A;
    g_pk1[i] = make_float4(px, py, st, any ? area : -area);
    g_cnt[i] = 0;
}

// ---------------- kernel A: pairwise -> float2 {iou, cost} -----------------
__global__ void __launch_bounds__(256) pair_kernel() {
    __shared__ float4 sb[32], sm[32];
    __shared__ int soff[32];
    int tid = threadIdx.x;
    int j0 = blockIdx.y * 32;
    if (tid < 32) {
        sb[tid]   = g_gtbox[j0 + tid];
        sm[tid]   = g_gtmeta[j0 + tid];
        soff[tid] = g_goff[j0 + tid];
    }
    __syncthreads();
    int i = blockIdx.x * 256 + tid;
    if (i >= N_P) return;

    float4 A = g_pk0[i];
    float4 P = g_pk1[i];
    bool valid = P.w > 0.0f;
    int ofs = j0 * N_P + i;

    #pragma unroll 4
    for (int jj = 0; jj < 32; jj++) {
        float4 b  = sb[jj];
        float4 m4 = sm[jj];
        float iou = iou_of(A, P.w, b, m4.x);
        float cost = 1e8f;
        if (valid) {
            int o = soff[jj] + i;
            float l = g_lT[o], s = g_sT[o], mm = g_mT[o];
            cost = cost_of(iou, P.x, P.y, P.z, m4.y, m4.z, l, s, mm);
        }
        g_pc[ofs] = make_float2(iou, cost);
        ofs += N_P;
    }
}

// ---------------- bitonic top-16 merge primitives --------------------------
__device__ __forceinline__ void merge_iou(float* a, const float* o) {
    float c[LEN];
    #pragma unroll
    for (int k = 0; k < LEN; k++) c[k] = fmaxf(a[k], o[LEN-1-k]);
    #pragma unroll
    for (int s = LEN/2; s > 0; s >>= 1) {
        #pragma unroll
        for (int k = 0; k < LEN; k++) {
            if ((k & s) == 0) {
                float lo = c[k], hi = c[k+s];
                c[k]   = fmaxf(lo, hi);
                c[k+s] = fminf(lo, hi);
            }
        }
    }
    #pragma unroll
    for (int k = 0; k < LEN; k++) a[k] = c[k];
}

__device__ __forceinline__ void merge_key(u64* a, const u64* o) {
    u64 c[LEN];
    #pragma unroll
    for (int k = 0; k < LEN; k++) {
        u64 x = a[k], y = o[LEN-1-k];
        c[k] = (x < y) ? x : y;
    }
    #pragma unroll
    for (int s = LEN/2; s > 0; s >>= 1) {
        #pragma unroll
        for (int k = 0; k < LEN; k++) {
            if ((k & s) == 0) {
                u64 lo = c[k], hi = c[k+s];
                u64 mn = (lo < hi) ? lo : hi;
                u64 mx = (lo < hi) ? hi : lo;
                c[k] = mn; c[k+s] = mx;
            }
        }
    }
    #pragma unroll
    for (int k = 0; k < LEN; k++) a[k] = c[k];
}

__device__ __forceinline__ void shfl_merge(u64* ck, float* vi, int off) {
    u64 ok[LEN]; float ovi[LEN];
    #pragma unroll
    for (int k = 0; k < LEN; k++) {
        ok [k] = __shfl_xor_sync(0xFFFFFFFFu, ck[k], off);
        ovi[k] = __shfl_xor_sync(0xFFFFFFFFu, vi[k], off);
    }
    merge_key(ck, ok);
    merge_iou(vi, ovi);
}

// ---------------- kernel T1: per-(GT, half) top-13 from matrix -------------
__global__ void __launch_bounds__(256, 2) topk_p1_kernel() {
    int bid = blockIdx.x;
    int j = bid >> 1, part = bid & 1;
    int tid = threadIdx.x;
    int ibase = part * CHUNK;
    const float2* __restrict__ pc = g_pc + (size_t)j * N_P + ibase;

    float vi[LEN]; u64 ck[LEN];
    #pragma unroll
    for (int k = 0; k < LEN; k++) { vi[k] = -1.0f; ck[k] = 0xFFFFFFFFFFFFFFFFull; }

    #pragma unroll 2
    for (int t = tid; t < CHUNK; t += 256) {
        float2 p = __ldg(pc + t);
        if (p.x > vi[LEN-1]) {
            vi[LEN-1] = p.x;
            #pragma unroll
            for (int k = LEN-1; k > 0; k--)
                if (vi[k] > vi[k-1]) { float tmp = vi[k-1]; vi[k-1] = vi[k]; vi[k] = tmp; }
        }
        u64 key = (((u64)__float_as_uint(p.y)) << 32) | (unsigned)(ibase + t);
        if (key < ck[LEN-1]) {
            ck[LEN-1] = key;
            #pragma unroll
            for (int k = LEN-1; k > 0; k--)
                if (ck[k] < ck[k-1]) { u64 tmp = ck[k-1]; ck[k-1] = ck[k]; ck[k] = tmp; }
        }
    }

    // warp butterfly merge (5 levels)
    #pragma unroll
    for (int off = 1; off < 32; off <<= 1) shfl_merge(ck, vi, off);

    // cross-warp merge (8 warp lists) in warp 0
    __shared__ u64 s_ck[8][LEN]; __shared__ float s_vi[8][LEN];
    int w = tid >> 5, lane = tid & 31;
    if (lane == 0) {
        #pragma unroll
        for (int k = 0; k < LEN; k++) { s_ck[w][k] = ck[k]; s_vi[w][k] = vi[k]; }
    }
    __syncthreads();
    if (w == 0) {
        if (lane < 8) {
            #pragma unroll
            for (int k = 0; k < LEN; k++) { ck[k] = s_ck[lane][k]; vi[k] = s_vi[lane][k]; }
        } else {
            #pragma unroll
            for (int k = 0; k < LEN; k++) { ck[k] = 0xFFFFFFFFFFFFFFFFull; vi[k] = -1.0f; }
        }
        shfl_merge(ck, vi, 1);
        shfl_merge(ck, vi, 2);
        shfl_merge(ck, vi, 4);
        if (lane == 0) {
            int base = bid * 16;
            #pragma unroll
            for (int k = 0; k < KK; k++) {
                g_skey[base + k] = ck[k];
                g_siou[base + k] = vi[k];
            }
        }
    }
}

// ---------------- kernel T2: merge halves, dynamic_ks, scatter -------------
__global__ void topk_p2_kernel() {
    int j = threadIdx.x;   // 256 GTs, 1 block
    const u64*   ka = g_skey + (j * 2)     * 16;
    const u64*   kb = g_skey + (j * 2 + 1) * 16;
    const float* va = g_siou + (j * 2)     * 16;
    const float* vb = g_siou + (j * 2 + 1) * 16;

    // iou: merge two descending lists, sum first 13 in sorted (desc) order
    float sum = 0.0f;
    {
        int a = 0, b = 0;
        #pragma unroll
        for (int r = 0; r < KK; r++) {
            float fa = va[a], fb = vb[b];
            if (fa >= fb) { sum += fa; a++; }
            else          { sum += fb; b++; }
        }
    }
    int ks = (int)sum;
    if (ks < 1)  ks = 1;
    if (ks > KK) ks = KK;

    // cost: merge two ascending key lists, scatter first ks candidates
    {
        int a = 0, b = 0;
        #pragma unroll
        for (int r = 0; r < KK; r++) {
            u64 x = ka[a], y = kb[b];
            u64 key;
            if (x < y) { key = x; a++; } else { key = y; b++; }
            if (r < ks) {
                int i = (int)(key & 0xFFFFFFFFull);
                atomicAdd(&g_cnt[i], 1);
                g_mgt[i] = j;       // racy only when cnt>1 (recomputed below)
            }
        }
    }
}

// ---------------- kernel R: resolve per-prior assignment -------------------
__global__ void __launch_bounds__(256) resolve_kernel(float* __restrict__ out) {
    int i = blockIdx.x * 256 + threadIdx.x;
    if (i >= N_P) return;
    float4 P = g_pk1[i];
    bool valid = P.w > 0.0f;
    int c = g_cnt[i];
    int gsel = 0;
    bool fg = false;
    if (c == 1) {
        gsel = g_mgt[i];
        fg = true;
    } else if (c > 1) {
        fg = true;
        float best = 3.4e38f;
        for (int j = 0; j < N_G; j++) {
            float cj = g_pc[(size_t)j * N_P + i].y;
            if (cj < best) { best = cj; gsel = j; }   // first-min -> lowest index
        }
    }
    float iou = 0.0f;
    if (fg) iou = g_pc[(size_t)gsel * N_P + i].x;
    bool fin = fg && valid;
    out[i]           = fin ? (float)(gsel + 1)   : 0.0f;
    out[N_P + i]     = fin ? iou                 : -1e8f;
    out[2*N_P + i]   = fin ? (float)g_glab[gsel] : -1.0f;
}

// ---------------- launch ----------------------------------------------------
extern "C" void kernel_launch(void* const* d_in, const int* in_sizes, int n_in,
                              void* d_out, int out_size) {
    const float* pred_scores = (const float*)d_in[0];
    const float* priors      = (const float*)d_in[1];
    const float* pred_bboxes = (const float*)d_in[2];
    const float* gt_bboxes   = (const float*)d_in[3];
    const int*   gt_labels   = (const int*)  d_in[4];

    prep_gt_kernel<<<1, 256>>>(gt_bboxes, gt_labels);
    prep_scores_kernel<<<N_P / 32, 256>>>(pred_scores);
    prep_priors_kernel<<<(N_P + 255) / 256, 256>>>(priors, pred_bboxes);
    dim3 gA((N_P + 255) / 256, 8);
    pair_kernel<<<gA, 256>>>();
    topk_p1_kernel<<<N_G * SPLIT, 256>>>();
    topk_p2_kernel<<<1, 256>>>();
    resolve_kernel<<<(N_P + 255) / 256, 256>>>((float*)d_out);
}

// round 4
// speedup vs baseline: 1.6359x; 1.1024x over previous
#include <cuda_runtime.h>
#include <math.h>
#include <stdint.h>

#define N_P 33600
#define N_G 256
#define N_C 80
#define KK  13
#define LEN 16
#define SPLIT 2
#define CHUNK (N_P / SPLIT)

typedef unsigned long long u64;
typedef unsigned int u32;

// ---------------- scratch (device globals; no runtime allocation) ----------
__device__ float2 g_pc [(size_t)N_G * N_P];   // column-major {iou, cost}
__device__ float  g_lT [(size_t)N_C * N_P];   // logits, class-major
__device__ float  g_sT [(size_t)N_C * N_P];   // sigmoid(logit)
__device__ float  g_mT [(size_t)N_C * N_P];   // softplus part of BCE
__device__ float4 g_pk0[N_P];                 // pred bbox x1,y1,x2,y2
__device__ float4 g_pk1[N_P];                 // px, py, 1/stride, +-area (sign = valid)
__device__ float4 g_gtbox [N_G];
__device__ float4 g_gtmeta[N_G];              // area, cx, cy, pad
__device__ float4 g_vbox  [N_G];
__device__ int    g_glab  [N_G];
__device__ int    g_goff  [N_G];              // glab[j] * N_P
__device__ int    g_cnt [N_P];
__device__ int    g_mgt [N_P];
__device__ u64    g_skey[N_G * SPLIT * 16];
__device__ float  g_siou[N_G * SPLIT * 16];

// ---------------- fast approx intrinsics ------------------------------------
__device__ __forceinline__ float ex2a(float x){ float r; asm("ex2.approx.f32 %0,%1;" : "=f"(r) : "f"(x)); return r; }
__device__ __forceinline__ float lg2a(float x){ float r; asm("lg2.approx.f32 %0,%1;" : "=f"(r) : "f"(x)); return r; }
__device__ __forceinline__ float sqrta(float x){ float r; asm("sqrt.approx.f32 %0,%1;" : "=f"(r) : "f"(x)); return r; }
__device__ __forceinline__ float rcpa(float x){ float r; asm("rcp.approx.f32 %0,%1;" : "=f"(r) : "f"(x)); return r; }

// ---------------- math helpers ----------------------------------------------
// fast iou: ordering/sum only (never emitted as output)
__device__ __forceinline__ float iou_fast(float4 A, float Pw, float4 b, float area_b) {
    float area_a = fabsf(Pw);
    float ltx = fmaxf(A.x, b.x), lty = fmaxf(A.y, b.y);
    float rbx = fminf(A.z, b.z), rby = fminf(A.w, b.w);
    float w = fmaxf(rbx - ltx, 0.0f), h = fmaxf(rby - lty, 0.0f);
    float inter = w * h;
    float uni = (area_a + area_b) - inter;
    return inter * rcpa(fmaxf(uni, 1e-6f));
}

// exact iou: bit-identical to rounds 1-3 / reference (output path)
__device__ __forceinline__ float iou_exact(float4 A, float Pw, float4 b, float area_b) {
    float area_a = fabsf(Pw);
    float ltx = fmaxf(A.x, b.x), lty = fmaxf(A.y, b.y);
    float rbx = fminf(A.z, b.z), rby = fminf(A.w, b.w);
    float w = fmaxf(rbx - ltx, 0.0f), h = fmaxf(rby - lty, 0.0f);
    float inter = w * h;
    float uni = (area_a + area_b) - inter;
    return __fdiv_rn(inter, fmaxf(uni, 1e-6f));
}

__device__ __forceinline__ float cost_fast(float iou, float px, float py, float inv_st,
                                           float cx, float cy,
                                           float l, float s, float mm) {
    float dx = px - cx, dy = py - cy;
    float d2 = __fmaf_rn(dx, dx, dy * dy);
    float dist = sqrta(d2) * inv_st;
    // 10^(dist-3) = 2^(dist*log2(10) - 3*log2(10))
    float scp = ex2a(__fmaf_rn(dist, 3.321928094887362f, -9.965784284662087f));
    float d = iou - s;
    float scale = d * d;
    float bce = __fmaf_rn(-l, iou, mm);
    // -3*ln(iou+eps) = lg2(iou+eps) * (-3*ln2)
    float ic = lg2a(iou + 1e-7f) * -2.0794415416798357f;
    return __fmaf_rn(bce, scale, ic + scp);
}

// ---------------- kernel G: GT preprocessing -------------------------------
__global__ void prep_gt_kernel(const float* __restrict__ gtb,
                               const int*   __restrict__ glab) {
    int j = threadIdx.x;
    if (j < N_G) {
        float x1 = gtb[j*4+0], y1 = gtb[j*4+1];
        float x2 = gtb[j*4+2], y2 = gtb[j*4+3];
        g_gtbox[j] = make_float4(x1, y1, x2, y2);
        float area = (x2 - x1) * (y2 - y1);
        bool pad = ((x1 + y1) + (x2 + y2)) > 0.0f;
        g_gtmeta[j] = make_float4(area, (x1 + x2) * 0.5f, (y1 + y2) * 0.5f,
                                  pad ? 1.0f : 0.0f);
        g_vbox[j] = pad ? make_float4(x1, y1, x2, y2)
                        : make_float4(1e30f, 1e30f, -1e30f, -1e30f);
        int lab = glab[j];
        g_glab[j] = lab;
        g_goff[j] = lab * N_P;
    }
}

// ---------------- kernel S: sigmoid/softplus, transposed (tiled, approx) ---
__global__ void __launch_bounds__(256) prep_scores_kernel(const float* __restrict__ ps) {
    __shared__ float sh[80][33];
    int tid = threadIdx.x;
    int i0 = blockIdx.x * 32;
    const float* base = ps + (size_t)i0 * N_C;
    #pragma unroll
    for (int t = tid; t < 32 * 80; t += 256) {
        int i_loc = t / 80;
        int c = t - i_loc * 80;
        sh[c][i_loc] = base[t];
    }
    __syncthreads();
    int i_loc = tid & 31;
    int cbase = tid >> 5;
    #pragma unroll
    for (int cc = cbase; cc < 80; cc += 8) {
        float l = sh[cc][i_loc];
        // e = exp(-|l|) = 2^(-|l|*log2e)
        float e = ex2a(fabsf(l) * -1.4426950408889634f);
        float inv = rcpa(1.0f + e);
        float sig = (l >= 0.0f) ? inv : e * inv;
        // log1p(e) = lg2(1+e)*ln2
        float m = __fmaf_rn(lg2a(1.0f + e), 0.6931471805599453f, fmaxf(l, 0.0f));
        int o = cc * N_P + i0 + i_loc;
        g_lT[o] = l;
        g_sT[o] = sig;
        g_mT[o] = m;
    }
}

// ---------------- kernel P: pack priors + valid mask + zero counters -------
__global__ void __launch_bounds__(256) prep_priors_kernel(const float* __restrict__ priors,
                                                          const float* __restrict__ pb) {
    __shared__ float4 svb[N_G];
    int tid = threadIdx.x;
    svb[tid] = g_vbox[tid];
    __syncthreads();
    int i = blockIdx.x * 256 + tid;
    if (i >= N_P) return;
    float4 PR = ((const float4*)priors)[i];
    float4 A  = ((const float4*)pb)[i];
    float px = PR.x, py = PR.y;
    bool any = false;
    #pragma unroll 8
    for (int j = 0; j < N_G; j++) {
        float4 B = svb[j];
        any |= (px > B.x) && (py > B.y) && (px < B.z) && (py < B.w);
    }
    float area = (A.z - A.x) * (A.w - A.y);
    g_pk0[i] = A;
    g_pk1[i] = make_float4(px, py, rcpa(PR.z), any ? area : -area);
    g_cnt[i] = 0;
}

// ---------------- kernel A: pairwise -> float2 {iou, cost} -----------------
__global__ void __launch_bounds__(256) pair_kernel() {
    __shared__ float4 sb[32], sm[32];
    __shared__ int soff[32];
    int tid = threadIdx.x;
    int j0 = blockIdx.y * 32;
    if (tid < 32) {
        sb[tid]   = g_gtbox[j0 + tid];
        sm[tid]   = g_gtmeta[j0 + tid];
        soff[tid] = g_goff[j0 + tid];
    }
    __syncthreads();
    int i = blockIdx.x * 256 + tid;
    if (i >= N_P) return;

    float4 A = g_pk0[i];
    float4 P = g_pk1[i];
    bool valid = P.w > 0.0f;
    int ofs = j0 * N_P + i;

    #pragma unroll 4
    for (int jj = 0; jj < 32; jj++) {
        float4 b  = sb[jj];
        float4 m4 = sm[jj];
        float iou = iou_fast(A, P.w, b, m4.x);
        float cost = 1e8f;
        if (valid) {
            int o = soff[jj] + i;
            float l = __ldg(&g_lT[o]), s = __ldg(&g_sT[o]), mm = __ldg(&g_mT[o]);
            cost = cost_fast(iou, P.x, P.y, P.z, m4.y, m4.z, l, s, mm);
        }
        g_pc[ofs] = make_float2(iou, cost);
        ofs += N_P;
    }
}

// ---------------- bitonic top-16 merge primitives --------------------------
__device__ __forceinline__ void merge_iou(float* a, const float* o) {
    float c[LEN];
    #pragma unroll
    for (int k = 0; k < LEN; k++) c[k] = fmaxf(a[k], o[LEN-1-k]);
    #pragma unroll
    for (int s = LEN/2; s > 0; s >>= 1) {
        #pragma unroll
        for (int k = 0; k < LEN; k++) {
            if ((k & s) == 0) {
                float lo = c[k], hi = c[k+s];
                c[k]   = fmaxf(lo, hi);
                c[k+s] = fminf(lo, hi);
            }
        }
    }
    #pragma unroll
    for (int k = 0; k < LEN; k++) a[k] = c[k];
}

__device__ __forceinline__ void merge_key(u64* a, const u64* o) {
    u64 c[LEN];
    #pragma unroll
    for (int k = 0; k < LEN; k++) {
        u64 x = a[k], y = o[LEN-1-k];
        c[k] = (x < y) ? x : y;
    }
    #pragma unroll
    for (int s = LEN/2; s > 0; s >>= 1) {
        #pragma unroll
        for (int k = 0; k < LEN; k++) {
            if ((k & s) == 0) {
                u64 lo = c[k], hi = c[k+s];
                u64 mn = (lo < hi) ? lo : hi;
                u64 mx = (lo < hi) ? hi : lo;
                c[k] = mn; c[k+s] = mx;
            }
        }
    }
    #pragma unroll
    for (int k = 0; k < LEN; k++) a[k] = c[k];
}

__device__ __forceinline__ void shfl_merge(u64* ck, float* vi, int off) {
    u64 ok[LEN]; float ovi[LEN];
    #pragma unroll
    for (int k = 0; k < LEN; k++) {
        ok [k] = __shfl_xor_sync(0xFFFFFFFFu, ck[k], off);
        ovi[k] = __shfl_xor_sync(0xFFFFFFFFu, vi[k], off);
    }
    merge_key(ck, ok);
    merge_iou(vi, ovi);
}

// ---------------- kernel T1: per-(GT, half) top-13 from matrix -------------
__global__ void __launch_bounds__(256) topk_p1_kernel() {
    int bid = blockIdx.x;
    int j = bid >> 1, part = bid & 1;
    int tid = threadIdx.x;
    int ibase = part * CHUNK;
    const float2* __restrict__ pc = g_pc + (size_t)j * N_P + ibase;

    float vi[LEN]; u64 ck[LEN];
    #pragma unroll
    for (int k = 0; k < LEN; k++) { vi[k] = -1.0f; ck[k] = 0xFFFFFFFFFFFFFFFFull; }

    #pragma unroll 4
    for (int t = tid; t < CHUNK; t += 256) {
        float2 p = __ldg(pc + t);
        if (p.x > vi[LEN-1]) {
            vi[LEN-1] = p.x;
            #pragma unroll
            for (int k = LEN-1; k > 0; k--)
                if (vi[k] > vi[k-1]) { float tmp = vi[k-1]; vi[k-1] = vi[k]; vi[k] = tmp; }
        }
        u64 key = (((u64)__float_as_uint(p.y)) << 32) | (u32)(ibase + t);
        if (key < ck[LEN-1]) {
            ck[LEN-1] = key;
            #pragma unroll
            for (int k = LEN-1; k > 0; k--)
                if (ck[k] < ck[k-1]) { u64 tmp = ck[k-1]; ck[k-1] = ck[k]; ck[k] = tmp; }
        }
    }

    #pragma unroll
    for (int off = 1; off < 32; off <<= 1) shfl_merge(ck, vi, off);

    __shared__ u64 s_ck[8][LEN]; __shared__ float s_vi[8][LEN];
    int w = tid >> 5, lane = tid & 31;
    if (lane == 0) {
        #pragma unroll
        for (int k = 0; k < LEN; k++) { s_ck[w][k] = ck[k]; s_vi[w][k] = vi[k]; }
    }
    __syncthreads();
    if (w == 0) {
        if (lane < 8) {
            #pragma unroll
            for (int k = 0; k < LEN; k++) { ck[k] = s_ck[lane][k]; vi[k] = s_vi[lane][k]; }
        } else {
            #pragma unroll
            for (int k = 0; k < LEN; k++) { ck[k] = 0xFFFFFFFFFFFFFFFFull; vi[k] = -1.0f; }
        }
        shfl_merge(ck, vi, 1);
        shfl_merge(ck, vi, 2);
        shfl_merge(ck, vi, 4);
        if (lane == 0) {
            int base = bid * 16;
            #pragma unroll
            for (int k = 0; k < KK; k++) {
                g_skey[base + k] = ck[k];
                g_siou[base + k] = vi[k];
            }
        }
    }
}

// ---------------- kernel T2: merge halves, dynamic_ks, scatter -------------
__global__ void topk_p2_kernel() {
    int j = threadIdx.x;   // 256 GTs, 1 block
    const u64*   ka = g_skey + (j * 2)     * 16;
    const u64*   kb = g_skey + (j * 2 + 1) * 16;
    const float* va = g_siou + (j * 2)     * 16;
    const float* vb = g_siou + (j * 2 + 1) * 16;

    float sum = 0.0f;
    {
        int a = 0, b = 0;
        #pragma unroll
        for (int r = 0; r < KK; r++) {
            float fa = va[a], fb = vb[b];
            if (fa >= fb) { sum += fa; a++; }
            else          { sum += fb; b++; }
        }
    }
    int ks = (int)sum;
    if (ks < 1)  ks = 1;
    if (ks > KK) ks = KK;

    {
        int a = 0, b = 0;
        #pragma unroll
        for (int r = 0; r < KK; r++) {
            u64 x = ka[a], y = kb[b];
            u64 key;
            if (x < y) { key = x; a++; } else { key = y; b++; }
            if (r < ks) {
                int i = (int)(key & 0xFFFFFFFFull);
                atomicAdd(&g_cnt[i], 1);
                g_mgt[i] = j;
            }
        }
    }
}

// ---------------- kernel R: resolve per-prior assignment -------------------
__global__ void __launch_bounds__(256) resolve_kernel(float* __restrict__ out) {
    int i = blockIdx.x * 256 + threadIdx.x;
    if (i >= N_P) return;
    float4 P = g_pk1[i];
    float4 A = g_pk0[i];
    bool valid = P.w > 0.0f;
    int c = g_cnt[i];
    int gsel = 0;
    bool fg = false;
    if (c == 1) {
        gsel = g_mgt[i];
        fg = true;
    } else if (c > 1) {
        fg = true;
        float best = 3.4e38f;
        for (int j = 0; j < N_G; j++) {
            float cj = g_pc[(size_t)j * N_P + i].y;
            if (cj < best) { best = cj; gsel = j; }   // first-min -> lowest index
        }
    }
    float iou = 0.0f;
    if (fg) {
        // exact recompute for output fidelity
        iou = iou_exact(A, P.w, g_gtbox[gsel], g_gtmeta[gsel].x);
    }
    bool fin = fg && valid;
    out[i]           = fin ? (float)(gsel + 1)   : 0.0f;
    out[N_P + i]     = fin ? iou                 : -1e8f;
    out[2*N_P + i]   = fin ? (float)g_glab[gsel] : -1.0f;
}

// ---------------- launch ----------------------------------------------------
extern "C" void kernel_launch(void* const* d_in, const int* in_sizes, int n_in,
                              void* d_out, int out_size) {
    const float* pred_scores = (const float*)d_in[0];
    const float* priors      = (const float*)d_in[1];
    const float* pred_bboxes = (const float*)d_in[2];
    const float* gt_bboxes   = (const float*)d_in[3];
    const int*   gt_labels   = (const int*)  d_in[4];

    prep_gt_kernel<<<1, 256>>>(gt_bboxes, gt_labels);
    prep_scores_kernel<<<N_P / 32, 256>>>(pred_scores);
    prep_priors_kernel<<<(N_P + 255) / 256, 256>>>(priors, pred_bboxes);
    dim3 gA((N_P + 255) / 256, 8);
    pair_kernel<<<gA, 256>>>();
    topk_p1_kernel<<<N_G * SPLIT, 256>>>();
    topk_p2_kernel<<<1, 256>>>();
    resolve_kernel<<<(N_P + 255) / 256, 256>>>((float*)d_out);
}